// round 14
// baseline (speedup 1.0000x reference)
#include <cuda_runtime.h>
#include <cuda_fp16.h>
#include <cstdint>

#define VV 8000
#define DD 128
#define UU 256
#define BB 32
#define SS 256
#define H3 768
#define H6 1536
#define MR 8192   // B*S
#define KC 1600   // WfT split-K chunk (x5)
#define NSPLIT 5

// ---------------- scratch (static device allocations; no cudaMalloc) ---------
__device__ __align__(128) __half g_w1h[2 * UU * VV];    // fp16(W1) [512,8000]
__device__ __align__(128) __half g_w2t[VV * VV];        // fp16(W2^T) [8000,8000]
__device__ __align__(128) __half g_embh[VV * DD];       // fp16(emb)
__device__ __align__(128) __half g_wcatt[H6 * DD];      // fp16([W_f|W_b]^T)
__device__ __align__(128) float  g_bcat[H6];
__device__ __align__(128) float  g_embw[VV * H6];       // emb proj + bias (fp32)
__device__ __align__(128) __half g_hcat[MR * 2 * UU];   // fp16 GRU outputs
__device__ __align__(128) __half g_wfth[VV * 2 * UU];   // fp16((W1@W2)^T) [8000,512]
__device__ __align__(128) float  g_partk[NSPLIT * VV * 2 * UU];  // split-K partials
__device__ __align__(128) float  g_bf[VV];
__device__ __align__(128) float  g_zb[2 * UU];          // zero bias (never written)
__device__ __align__(128) float  g_uperm[2 * 4 * UU * 192];

// packed f32x2 helpers (sm_103a)
__device__ __forceinline__ unsigned long long pack2(float x, float y) {
    unsigned long long r;
    asm("mov.b64 %0, {%1,%2};" : "=l"(r) : "f"(x), "f"(y));
    return r;
}
__device__ __forceinline__ float2 unpack2(unsigned long long v) {
    float2 r;
    asm("mov.b64 {%0,%1}, %2;" : "=f"(r.x), "=f"(r.y) : "l"(v));
    return r;
}
#define FMA2(acc, a, b) \
    asm("fma.rn.f32x2 %0, %1, %2, %0;" : "+l"(acc) : "l"(a), "l"(b))

// DSMEM / cluster helpers
__device__ __forceinline__ uint32_t mapa_u32(uint32_t laddr, uint32_t rank) {
    uint32_t r;
    asm("mapa.shared::cluster.u32 %0, %1, %2;" : "=r"(r) : "r"(laddr), "r"(rank));
    return r;
}
#define CLUSTER_ARRIVE() asm volatile("barrier.cluster.arrive.aligned;" ::: "memory")
#define CLUSTER_WAIT()   asm volatile("barrier.cluster.wait.aligned;" ::: "memory")

// async remote store with mbarrier tx completion (sm_90+)
#define ST_ASYNC_U64(raddr, v, rmbar) \
    asm volatile("st.async.shared::cluster.mbarrier::complete_tx::bytes.u64 [%0], %1, [%2];" \
                 :: "r"(raddr), "l"(v), "r"(rmbar) : "memory")

#define MBARRIER_INIT(addr, cnt) \
    asm volatile("mbarrier.init.shared.b64 [%0], %1;" :: "r"((uint32_t)(addr)), "r"((uint32_t)(cnt)) : "memory")
#define MBARRIER_EXPECT_TX(addr, tx) \
    asm volatile("mbarrier.arrive.expect_tx.shared.b64 _, [%0], %1;" \
                 :: "r"((uint32_t)(addr)), "r"((uint32_t)(tx)) : "memory")
#define MBARRIER_WAIT_PARITY(addr, par) do {                                   \
    uint32_t _m = (uint32_t)(addr); uint32_t _p = (uint32_t)(par);             \
    asm volatile(                                                              \
        "{\n\t.reg .pred P1;\n\t"                                              \
        "WL_%=:\n\t"                                                           \
        "mbarrier.try_wait.parity.acquire.cta.shared::cta.b64 P1, [%0], %1, 0x989680;\n\t" \
        "@P1 bra.uni WD_%=;\n\t"                                               \
        "bra.uni WL_%=;\n\t"                                                   \
        "WD_%=:\n\t}"                                                          \
        :: "r"(_m), "r"(_p) : "memory");                                       \
} while (0)

// ---------------- fused prep + W2-transpose kernel ----------------------------
#define P_W1   (2 * UU * VV / 4)
#define P_EMB  (VV * DD / 4)
#define P_WCAT (H6 * DD)
#define P_U    (2 * 4 * UU * 192)
#define P_TOT  (P_W1 + P_EMB + P_WCAT + P_U)
#define TR_BLK (VV / 32 * VV / 32)     // 62500
#define PREP_BLK ((P_TOT + 255) / 256)
#define PREPTR_GRID (TR_BLK + PREP_BLK)

__global__ void __launch_bounds__(256) prep_tr(
    const float* __restrict__ W2, __half* __restrict__ w2t,
    const float* __restrict__ W1, __half* __restrict__ w1h,
    const float* __restrict__ emb, __half* __restrict__ embh,
    const float* __restrict__ Wf_, const float* __restrict__ Wb_,
    const float* __restrict__ bfb, const float* __restrict__ bbb,
    __half* __restrict__ wcatt, float* __restrict__ bcat,
    const float* __restrict__ Uf, const float* __restrict__ Ub,
    float* __restrict__ uperm)
{
    __shared__ float t[32][33];
    int b = blockIdx.x;
    int tid = threadIdx.x;
    if (b < TR_BLK) {
        int bx = (b % (VV / 32)) * 32;
        int by = (b / (VV / 32)) * 32;
        int x = tid & 31, y0 = tid >> 5;
#pragma unroll
        for (int dy = 0; dy < 32; dy += 8)
            t[y0 + dy][x] = W2[(size_t)(by + y0 + dy) * VV + bx + x];
        __syncthreads();
#pragma unroll
        for (int dy = 0; dy < 32; dy += 8)
            w2t[(size_t)(bx + y0 + dy) * VV + by + x] = __float2half_rn(t[x][y0 + dy]);
        return;
    }
    int i = (b - TR_BLK) * 256 + tid;
    if (i < P_W1) {
        float4 v = ((const float4*)W1)[i];
        __half2 h0 = __floats2half2_rn(v.x, v.y);
        __half2 h1 = __floats2half2_rn(v.z, v.w);
        uint2 r;
        r.x = *reinterpret_cast<uint32_t*>(&h0);
        r.y = *reinterpret_cast<uint32_t*>(&h1);
        ((uint2*)w1h)[i] = r;
        return;
    }
    i -= P_W1;
    if (i < P_EMB) {
        float4 v = ((const float4*)emb)[i];
        __half2 h0 = __floats2half2_rn(v.x, v.y);
        __half2 h1 = __floats2half2_rn(v.z, v.w);
        uint2 r;
        r.x = *reinterpret_cast<uint32_t*>(&h0);
        r.y = *reinterpret_cast<uint32_t*>(&h1);
        ((uint2*)embh)[i] = r;
        return;
    }
    i -= P_EMB;
    if (i < P_WCAT) {
        int n = i / DD, k = i % DD;
        float v = (n < H3) ? Wf_[k * H3 + n] : Wb_[k * H3 + (n - H3)];
        wcatt[i] = __float2half_rn(v);
        if (i < H6)
            bcat[i] = (i < H3) ? bfb[i] : bbb[i - H3];
        return;
    }
    i -= P_WCAT;
    if (i < P_U) {
        int c = i % 192;
        int k = (i / 192) % UU;
        int r = (i / (192 * UU)) % 4;
        int dir = i / (192 * UU * 4);
        const float* Um = dir ? Ub : Uf;
        int col = (c < 64) ? (64 * r + c)
                : (c < 128) ? (UU + 64 * r + (c - 64))
                            : (2 * UU + 64 * r + (c - 128));
        uperm[i] = Um[k * H3 + col];
    }
}

// split-K reduce: wfth = fp16(sum of NSPLIT partials)
__global__ void wf_reduce(const float* __restrict__ partk, __half* __restrict__ wfth) {
    int i = blockIdx.x * 256 + threadIdx.x;
    const int n4 = VV * 2 * UU / 4;
    if (i >= n4) return;
    float4 s = ((const float4*)partk)[i];
#pragma unroll
    for (int z = 1; z < NSPLIT; z++) {
        float4 v = ((const float4*)(partk + (size_t)z * VV * 2 * UU))[i];
        s.x += v.x; s.y += v.y; s.z += v.z; s.w += v.w;
    }
    __half2 h0 = __floats2half2_rn(s.x, s.y);
    __half2 h1 = __floats2half2_rn(s.z, s.w);
    uint2 r;
    r.x = *reinterpret_cast<uint32_t*>(&h0);
    r.y = *reinterpret_cast<uint32_t*>(&h1);
    ((uint2*)wfth)[i] = r;
}

// ---------------- fp16 GEMM body (mma.sync m16n8k16, fp32 accum) --------------
#define HBM_ 128
#define HBN_ 256
#define HBK_ 32
#define HNST 4
#define HROWB 80
#define HASB (HBM_ * HROWB)
#define HBSB (HBN_ * HROWB)
#define HSTG (HASB + HBSB)
#define HGE_SMEM (HNST * HSTG)

__device__ __forceinline__ void gemm_body(
    const __half* __restrict__ A, int lda,
    const __half* __restrict__ Bt, int ldb,
    const float* __restrict__ bias, float* __restrict__ C,
    int M, int N, int K, int tile, unsigned char* sm)
{
    int ntiles = (N + HBN_ - 1) / HBN_;
    int mt = tile / ntiles, nt = tile % ntiles;
    int m0 = mt * HBM_, n0 = nt * HBN_;

    int tid = threadIdx.x;
    int lane = tid & 31;
    int wid = tid >> 5;
    int wm = wid >> 2;
    int wn = wid & 3;
    int g = lane >> 2;
    int t4 = lane & 3;

    uint32_t sbase = (uint32_t)__cvta_generic_to_shared(sm);

    float acc[4][8][4];
#pragma unroll
    for (int a = 0; a < 4; a++)
#pragma unroll
        for (int b = 0; b < 8; b++)
#pragma unroll
            for (int c = 0; c < 4; c++) acc[a][b][c] = 0.f;

    const int KT = K / HBK_;

    auto issue = [&](int kt, int slot) {
        int k0 = kt * HBK_;
        uint32_t ab = sbase + slot * HSTG;
        uint32_t bb = ab + HASB;
#pragma unroll
        for (int i = 0; i < 2; i++) {
            int ch = tid + i * 256;
            int r = ch >> 2, c16 = ch & 3;
            int ra = m0 + r; if (ra >= M) ra = M - 1;
            const __half* src = A + (size_t)ra * lda + k0 + c16 * 8;
            uint32_t dst = ab + (uint32_t)(r * HROWB + c16 * 16);
            asm volatile("cp.async.cg.shared.global [%0],[%1],16;\n" :: "r"(dst), "l"(src));
        }
#pragma unroll
        for (int i = 0; i < 4; i++) {
            int ch = tid + i * 256;
            int r = ch >> 2, c16 = ch & 3;
            int nb = n0 + r;
            int sz = (nb < N) ? 16 : 0;
            if (nb >= N) nb = N - 1;
            const __half* src = Bt + (size_t)nb * ldb + k0 + c16 * 8;
            uint32_t dst = bb + (uint32_t)(r * HROWB + c16 * 16);
            asm volatile("cp.async.cg.shared.global [%0],[%1],16,%2;\n" :: "r"(dst), "l"(src), "r"(sz));
        }
        asm volatile("cp.async.commit_group;\n");
    };

    auto docompute = [&](int slot) {
        const unsigned char* As = sm + slot * HSTG;
        const unsigned char* Bs = As + HASB;
#pragma unroll
        for (int kk = 0; kk < 2; kk++) {
            int kb = kk * 32 + t4 * 4;
            uint32_t af[4][4];
#pragma unroll
            for (int mi = 0; mi < 4; mi++) {
                int row = wm * 64 + mi * 16 + g;
                const unsigned char* p = As + row * HROWB + kb;
                af[mi][0] = *(const uint32_t*)(p);
                af[mi][1] = *(const uint32_t*)(p + 8 * HROWB);
                af[mi][2] = *(const uint32_t*)(p + 16);
                af[mi][3] = *(const uint32_t*)(p + 8 * HROWB + 16);
            }
            uint32_t bf[8][2];
#pragma unroll
            for (int ni = 0; ni < 8; ni++) {
                int nr = wn * 64 + ni * 8 + g;
                const unsigned char* p = Bs + nr * HROWB + kb;
                bf[ni][0] = *(const uint32_t*)(p);
                bf[ni][1] = *(const uint32_t*)(p + 16);
            }
#pragma unroll
            for (int mi = 0; mi < 4; mi++)
#pragma unroll
                for (int ni = 0; ni < 8; ni++) {
                    asm volatile(
                        "mma.sync.aligned.m16n8k16.row.col.f32.f16.f16.f32 "
                        "{%0,%1,%2,%3},{%4,%5,%6,%7},{%8,%9},{%0,%1,%2,%3};\n"
                        : "+f"(acc[mi][ni][0]), "+f"(acc[mi][ni][1]),
                          "+f"(acc[mi][ni][2]), "+f"(acc[mi][ni][3])
                        : "r"(af[mi][0]), "r"(af[mi][1]), "r"(af[mi][2]), "r"(af[mi][3]),
                          "r"(bf[ni][0]), "r"(bf[ni][1]));
                }
        }
    };

    issue(0, 0);
    if (KT > 1) issue(1, 1);
    if (KT > 2) issue(2, 2);

#pragma unroll 1
    for (int kt = 0; kt < KT; kt++) {
        if (kt + 1 < KT) {
            asm volatile("cp.async.wait_group %0;\n" :: "n"(HNST - 2));
        } else {
            asm volatile("cp.async.wait_group 0;\n");
        }
        __syncthreads();
        if (kt + HNST - 1 < KT)
            issue(kt + HNST - 1, (kt + HNST - 1) & (HNST - 1));
        docompute(kt & (HNST - 1));
    }

#pragma unroll
    for (int ni = 0; ni < 8; ni++) {
        int c = n0 + wn * 64 + ni * 8 + t4 * 2;
        if (c >= N) continue;
        float b0v = bias[c], b1v = bias[c + 1];
#pragma unroll
        for (int mi = 0; mi < 4; mi++) {
            int r = m0 + wm * 64 + mi * 16 + g;
            if (r >= M) continue;
            *reinterpret_cast<float2*>(&C[(size_t)r * N + c]) =
                make_float2(acc[mi][ni][0] + b0v, acc[mi][ni][1] + b1v);
            if (r + 8 < M)
                *reinterpret_cast<float2*>(&C[(size_t)(r + 8) * N + c]) =
                    make_float2(acc[mi][ni][2] + b0v, acc[mi][ni][3] + b1v);
        }
    }
}

// standalone GEMM (final logits)
__global__ void __launch_bounds__(256) gemm_h0(
    const __half* __restrict__ A, int lda, const __half* __restrict__ Bt, int ldb,
    const float* __restrict__ bias, float* __restrict__ C,
    int M, int N, int K)
{
    extern __shared__ __align__(16) unsigned char sm[];
    gemm_body(A, lda, Bt, ldb, bias, C, M, N, K, blockIdx.x, sm);
}

// ---------------- megaWE: WfT split-K + embW GEMM + bias fuse -----------------
#define NWFT  (NSPLIT * 126)     // 630
#define NEMB  378                // 63 x 6
#define NBIAS (VV / 8)           // 1000
#define MWE_GRID (NWFT + NEMB + NBIAS)

__global__ void __launch_bounds__(256) megaWE(
    const __half* __restrict__ w2t, const __half* __restrict__ w1h,
    float* __restrict__ partk, const float* __restrict__ zb,
    const __half* __restrict__ embh, const __half* __restrict__ wcatt,
    const float* __restrict__ bcat, float* __restrict__ embw,
    const float* __restrict__ b1, const float* __restrict__ b2,
    float* __restrict__ bf)
{
    extern __shared__ __align__(16) unsigned char sm[];
    int b = blockIdx.x;
    if (b < NWFT) {
        int kz = b / 126, t = b % 126;
        gemm_body(w2t + (size_t)kz * KC, VV,
                  w1h + (size_t)kz * KC, VV,
                  zb, partk + (size_t)kz * VV * 2 * UU,
                  VV, 2 * UU, KC, t, sm);
    } else if (b < NWFT + NEMB) {
        gemm_body(embh, DD, wcatt, DD, bcat, embw, VV, H6, DD, b - NWFT, sm);
    } else {
        int nb = b - NWFT - NEMB;
        int n = nb * 8 + (threadIdx.x >> 5);
        int lane = threadIdx.x & 31;
        const __half2* row = (const __half2*)(w2t + (size_t)n * VV);
        const float2* b1p = (const float2*)b1;
        float acc = 0.f;
#pragma unroll 5
        for (int i = 0; i < VV / 64; i++) {
            int idx = i * 32 + lane;
            float2 f = __half22float2(row[idx]);
            float2 bb = b1p[idx];
            acc += bb.x * f.x + bb.y * f.y;
        }
#pragma unroll
        for (int off = 16; off > 0; off >>= 1)
            acc += __shfl_xor_sync(0xFFFFFFFF, acc, off);
        if (lane == 0) bf[n] = acc + b2[n];
    }
}

// ---------------- GRU: 384 thr, per-batch software pipeline, compact U --------
// Per step, the two batch chains are processed sequentially; each chain's
// DSMEM round-trip hides under the other chain's compute, so mbarrier waits
// hit the fast path. Barriers re-armed immediately after each wait (margin =
// half-step + DSMEM transit, structural). Compact U smem holds only the
// 12 non-register rows per 32-k range: 196KB -> 72KB.
#define GRU_THREADS 384
#define UREG 20
#define UROWS_SM (256 * 12 / 32)                // 96 compact rows
#define GRU_SM_U    (UROWS_SM * 192 * 4)        // 73728
#define GRU_SM_PART (2 * 8 * 192 * 4)           // 12288
#define GRU_SM_H    (2 * 2 * UU * 8)            // 8192  [parity][batch][dim]
#define GRU_SMEM    (GRU_SM_U + GRU_SM_PART + GRU_SM_H + 32)

__global__ void __launch_bounds__(GRU_THREADS, 1) __cluster_dims__(4, 1, 1)
gru_scan(const float* __restrict__ embW, const float* __restrict__ uperm,
         const float* __restrict__ bf1, const float* __restrict__ bb1,
         const int* __restrict__ tokens, __half* __restrict__ hcat)
{
    extern __shared__ __align__(16) unsigned char smraw[];
    float* Us   = (float*)smraw;                                    // compact U
    float* part = (float*)(smraw + GRU_SM_U);                       // [2][8][192]
    unsigned long long* hbuf =
        (unsigned long long*)(smraw + GRU_SM_U + GRU_SM_PART);      // [2][2][256]
    uint32_t mb0 = (uint32_t)__cvta_generic_to_shared(
        smraw + GRU_SM_U + GRU_SM_PART + GRU_SM_H);                 // 4 barriers

    int tid  = threadIdx.x;
    int cid  = blockIdx.x >> 2;
    int rank = blockIdx.x & 3;
    int bp   = cid & 15;
    int dir  = cid >> 4;
    int b0   = bp * 2;
    const float* bv = dir ? bb1 : bf1;
    const float* usl = uperm + (size_t)(dir * 4 + rank) * UU * 192;

    // prologue: compact U rows (each range's rows UREG..31), h zero, barriers
    {
        const float4* src = (const float4*)usl;
        float4* dst = (float4*)Us;
        for (int i = tid; i < UROWS_SM * 48; i += GRU_THREADS) {
            int r = i / 48, c4 = i % 48;
            int gr = (r / 12) * 32 + UREG + (r % 12);
            dst[i] = src[gr * 48 + c4];
        }
        for (int i = tid; i < 2 * 2 * UU; i += GRU_THREADS) hbuf[i] = 0ull;
    }
    if (tid == 0) {
        for (int q = 0; q < 4; q++) MBARRIER_INIT(mb0 + q * 8, 1);
        // arm all 4 (batch 0/1 x parity 0/1) for their first use
        for (int q = 0; q < 4; q++) MBARRIER_EXPECT_TX(mb0 + q * 8, 2048);
    }
    __syncthreads();
    CLUSTER_ARRIVE();
    CLUSTER_WAIT();

    int kc = tid / 48;     // 0..7: k-range of 32
    int ct = tid % 48;     // 2 col-pairs (4 cols)
    int k0 = kc * 32;

    // register-resident U rows k0..k0+UREG (direct from global)
    ulonglong2 ur[UREG];
    {
        const ulonglong2* ug = (const ulonglong2*)usl;
#pragma unroll
        for (int kk = 0; kk < UREG; kk++)
            ur[kk] = ug[(size_t)(k0 + kk) * 48 + ct];
    }

    int j = rank * 64 + tid;   // valid for tid < 64 (update threads)
    float bz = 0.f, br = 0.f, bh = 0.f;
    if (tid < 64) { bz = bv[j]; br = bv[UU + j]; bh = bv[2 * UU + j]; }

    uint32_t hl = (uint32_t)__cvta_generic_to_shared(hbuf);
    uint32_t hpeer[4], mpeer[4];
#pragma unroll
    for (int r = 0; r < 4; r++) {
        hpeer[r] = mapa_u32(hl, r);
        mpeer[r] = mapa_u32(mb0, r);
    }

    int ph[4] = {0, 0, 0, 0};   // phase per barrier (bch*2 + parity)

    for (int i = 0; i < SS; i++) {
        int p = i & 1;

        // prefetch both batches' gate rows + tokens (hides global latency)
        float pz[2], pr[2], phx[2]; int tk[2]; size_t rb[2];
        if (tid < 64) {
            int s = dir ? (SS - 1 - i) : i;
#pragma unroll
            for (int bc = 0; bc < 2; bc++) {
                rb[bc] = (size_t)(b0 + bc) * SS + s;
                tk[bc] = tokens[rb[bc]];
                const float* xr = embW + (size_t)tk[bc] * H6 + dir * H3;
                pz[bc] = xr[j]; pr[bc] = xr[UU + j]; phx[bc] = xr[2 * UU + j];
            }
        }

#pragma unroll 1
        for (int bc = 0; bc < 2; bc++) {
            int bidx = bc * 2 + p;
            if (i > 0) {
                MBARRIER_WAIT_PARITY(mb0 + bidx * 8, ph[bidx]);
                ph[bidx] ^= 1;
                // re-arm for next use (txs arrive at step i+1; earliest after
                // our own st.async this step -> structural margin)
                if (tid == 0) MBARRIER_EXPECT_TX(mb0 + bidx * 8, 2048);
            }

            // ---- matvec for batch bc over h(p, bc) ----
            {
                unsigned long long a0 = 0, a1 = 0;
                const ulonglong2* h = (const ulonglong2*)(hbuf + (p * 2 + bc) * UU) + kc * 16;
#pragma unroll
                for (int kk = 0; kk < UREG / 2; kk++) {
                    ulonglong2 uA = ur[2 * kk];
                    ulonglong2 uB = ur[2 * kk + 1];
                    ulonglong2 hA = h[kk];
                    FMA2(a0, uA.x, hA.x); FMA2(a1, uA.y, hA.x);
                    FMA2(a0, uB.x, hA.y); FMA2(a1, uB.y, hA.y);
                }
                const ulonglong2* up = (const ulonglong2*)Us + (size_t)(kc * 12) * 48 + ct;
#pragma unroll
                for (int kk = UREG / 2; kk < 16; kk++) {
                    ulonglong2 uA = up[0];
                    ulonglong2 uB = up[48];
                    up += 96;
                    ulonglong2 hA = h[kk];
                    FMA2(a0, uA.x, hA.x); FMA2(a1, uA.y, hA.x);
                    FMA2(a0, uB.x, hA.y); FMA2(a1, uB.y, hA.y);
                }
                float2 p0 = unpack2(a0), p1 = unpack2(a1);
                ((float4*)(part + bc * 1536 + kc * 192))[ct] = make_float4(p0.x, p0.y, p1.x, p1.y);
            }
            __syncthreads();

            // ---- gate update for batch bc (64 threads; overlaps next matvec) ----
            if (tid < 64) {
                float iz = 0.f, ir = 0.f, ih = 0.f;
                const float* pb = part + bc * 1536;
#pragma unroll
                for (int q = 0; q < 8; q++) {
                    iz += pb[q * 192 + j - rank * 64];
                    ir += pb[q * 192 + 64 + j - rank * 64];
                    ih += pb[q * 192 + 128 + j - rank * 64];
                }

                float hold = ((const float*)&hbuf[(p * 2 + bc) * UU + j])[0];
                float z = 1.f / (1.f + __expf(-(pz[bc] + iz + bz)));
                float g = 1.f / (1.f + __expf(-(pr[bc] + ir + br)));
                float c = tanhf(phx[bc] + g * (ih + bh));
                float hn = z * hold + (1.f - z) * c;
                if (tk[bc] == 0) hn = hold;

                if (i < SS - 1) {
                    unsigned long long hd = pack2(hn, hn);
                    uint32_t off = (uint32_t)(((p ^ 1) * 2 + bc) * UU + j) * 8u;
                    uint32_t mboff = (uint32_t)((bc * 2 + (p ^ 1)) * 8);
#pragma unroll
                    for (int r = 0; r < 4; r++)
                        ST_ASYNC_U64(hpeer[r] + off, hd, mpeer[r] + mboff);
                }
                hcat[rb[bc] * (2 * UU) + dir * UU + j] = __float2half_rn(hn);
            }
            // no sync: part[bc] reuse ordered via the (bc, parity) mbarrier
        }
    }
    CLUSTER_ARRIVE();
    CLUSTER_WAIT();
}

// ---------------- host launcher ----------------------------------------------
extern "C" void kernel_launch(void* const* d_in, const int* in_sizes, int n_in,
                              void* d_out, int out_size)
{
    const int*   tokens = (const int*)d_in[0];
    const float* emb    = (const float*)d_in[1];
    const float* W_f    = (const float*)d_in[2];
    const float* U_f    = (const float*)d_in[3];
    const float* b_f    = (const float*)d_in[4];
    const float* W_b    = (const float*)d_in[5];
    const float* U_b    = (const float*)d_in[6];
    const float* b_b    = (const float*)d_in[7];
    const float* W1     = (const float*)d_in[8];
    const float* b1     = (const float*)d_in[9];
    const float* W2     = (const float*)d_in[10];
    const float* b2     = (const float*)d_in[11];
    float* out = (float*)d_out;

    __half *w1h, *w2t, *embh, *wcatt, *hcat, *wfth;
    float *bcat, *embw, *bfv, *uperm, *partk, *zb;
    cudaGetSymbolAddress((void**)&w1h,   g_w1h);
    cudaGetSymbolAddress((void**)&w2t,   g_w2t);
    cudaGetSymbolAddress((void**)&embh,  g_embh);
    cudaGetSymbolAddress((void**)&wcatt, g_wcatt);
    cudaGetSymbolAddress((void**)&bcat,  g_bcat);
    cudaGetSymbolAddress((void**)&embw,  g_embw);
    cudaGetSymbolAddress((void**)&hcat,  g_hcat);
    cudaGetSymbolAddress((void**)&wfth,  g_wfth);
    cudaGetSymbolAddress((void**)&bfv,   g_bf);
    cudaGetSymbolAddress((void**)&uperm, g_uperm);
    cudaGetSymbolAddress((void**)&partk, g_partk);
    cudaGetSymbolAddress((void**)&zb,    g_zb);

    cudaFuncSetAttribute(megaWE,  cudaFuncAttributeMaxDynamicSharedMemorySize, HGE_SMEM);
    cudaFuncSetAttribute(gemm_h0, cudaFuncAttributeMaxDynamicSharedMemorySize, HGE_SMEM);
    cudaFuncSetAttribute(gru_scan, cudaFuncAttributeMaxDynamicSharedMemorySize, GRU_SMEM);

    // 1) fused prep: W2 transpose (fp16) + fp16 conversions + concat + U permute
    prep_tr<<<PREPTR_GRID, 256>>>(W2, w2t, W1, w1h, emb, embh,
                                  W_f, W_b, b_f, b_b, wcatt, bcat,
                                  U_f, U_b, uperm);

    // 2) megaWE: WfT split-K GEMM (630) + embW GEMM (378) + bias fuse (1000)
    megaWE<<<MWE_GRID, 256, HGE_SMEM>>>(w2t, w1h, partk, zb,
                                        embh, wcatt, bcat, embw,
                                        b1, b2, bfv);

    // 3) reduce split-K partials -> fp16 WfT [8000,512]
    wf_reduce<<<(VV * 2 * UU / 4 + 255) / 256, 256>>>(partk, wfth);

    // 4) clustered bidirectional GRU scan (per-batch pipelined)
    gru_scan<<<128, GRU_THREADS, GRU_SMEM>>>(embw, uperm, b_f + H3, b_b + H3,
                                             tokens, hcat);

    // 5) logits = hcat @ Wf + bf -> output
    {
        int mtiles = MR / HBM_;                  // 64
        int ntiles = (VV + HBN_ - 1) / HBN_;     // 32
        gemm_h0<<<mtiles * ntiles, 256, HGE_SMEM>>>(hcat, 2 * UU, wfth, 2 * UU,
                                                    bfv, out, MR, VV, 2 * UU);
    }
}

// round 15
// speedup vs baseline: 1.2685x; 1.2685x over previous
#include <cuda_runtime.h>
#include <cuda_fp16.h>
#include <cstdint>

#define VV 8000
#define DD 128
#define UU 256
#define BB 32
#define SS 256
#define H3 768
#define H6 1536
#define MR 8192   // B*S
#define KC 1600   // WfT split-K chunk (x5)
#define NSPLIT 5

// ---------------- scratch (static device allocations; no cudaMalloc) ---------
__device__ __align__(128) __half g_w1h[2 * UU * VV];    // fp16(W1) [512,8000]
__device__ __align__(128) __half g_w2t[VV * VV];        // fp16(W2^T) [8000,8000]
__device__ __align__(128) __half g_embh[VV * DD];       // fp16(emb)
__device__ __align__(128) __half g_wcatt[H6 * DD];      // fp16([W_f|W_b]^T)
__device__ __align__(128) float  g_bcat[H6];
__device__ __align__(128) float  g_embw[VV * H6];       // emb proj + bias (fp32)
__device__ __align__(128) __half g_hcat[MR * 2 * UU];   // fp16 GRU outputs
__device__ __align__(128) __half g_wfth[VV * 2 * UU];   // fp16((W1@W2)^T) [8000,512]
__device__ __align__(128) float  g_partk[NSPLIT * VV * 2 * UU];  // split-K partials
__device__ __align__(128) float  g_bf[VV];
__device__ __align__(128) float  g_zb[2 * UU];          // zero bias (never written)
__device__ __align__(128) float  g_uperm[2 * 4 * UU * 192];

// ---------------- side stream + events (created at static init) ---------------
struct StreamInit {
    cudaStream_t s1;
    cudaEvent_t ev1, ev2;
    StreamInit() {
        cudaStreamCreateWithFlags(&s1, cudaStreamNonBlocking);
        cudaEventCreateWithFlags(&ev1, cudaEventDisableTiming);
        cudaEventCreateWithFlags(&ev2, cudaEventDisableTiming);
    }
};
static StreamInit g_si;

// packed f32x2 helpers (sm_103a)
__device__ __forceinline__ unsigned long long pack2(float x, float y) {
    unsigned long long r;
    asm("mov.b64 %0, {%1,%2};" : "=l"(r) : "f"(x), "f"(y));
    return r;
}
__device__ __forceinline__ float2 unpack2(unsigned long long v) {
    float2 r;
    asm("mov.b64 {%0,%1}, %2;" : "=f"(r.x), "=f"(r.y) : "l"(v));
    return r;
}
#define FMA2(acc, a, b) \
    asm("fma.rn.f32x2 %0, %1, %2, %0;" : "+l"(acc) : "l"(a), "l"(b))

// DSMEM / cluster helpers
__device__ __forceinline__ uint32_t mapa_u32(uint32_t laddr, uint32_t rank) {
    uint32_t r;
    asm("mapa.shared::cluster.u32 %0, %1, %2;" : "=r"(r) : "r"(laddr), "r"(rank));
    return r;
}
#define CLUSTER_ARRIVE() asm volatile("barrier.cluster.arrive.aligned;" ::: "memory")
#define CLUSTER_WAIT()   asm volatile("barrier.cluster.wait.aligned;" ::: "memory")

// async remote store with mbarrier tx completion (sm_90+)
#define ST_ASYNC_U64(raddr, v, rmbar) \
    asm volatile("st.async.shared::cluster.mbarrier::complete_tx::bytes.u64 [%0], %1, [%2];" \
                 :: "r"(raddr), "l"(v), "r"(rmbar) : "memory")

#define MBARRIER_INIT(addr, cnt) \
    asm volatile("mbarrier.init.shared.b64 [%0], %1;" :: "r"((uint32_t)(addr)), "r"((uint32_t)(cnt)) : "memory")
#define MBARRIER_EXPECT_TX(addr, tx) \
    asm volatile("mbarrier.arrive.expect_tx.shared.b64 _, [%0], %1;" \
                 :: "r"((uint32_t)(addr)), "r"((uint32_t)(tx)) : "memory")
#define MBARRIER_WAIT_PARITY(addr, par) do {                                   \
    uint32_t _m = (uint32_t)(addr); uint32_t _p = (uint32_t)(par);             \
    asm volatile(                                                              \
        "{\n\t.reg .pred P1;\n\t"                                              \
        "WL_%=:\n\t"                                                           \
        "mbarrier.try_wait.parity.acquire.cta.shared::cta.b64 P1, [%0], %1, 0x989680;\n\t" \
        "@P1 bra.uni WD_%=;\n\t"                                               \
        "bra.uni WL_%=;\n\t"                                                   \
        "WD_%=:\n\t}"                                                          \
        :: "r"(_m), "r"(_p) : "memory");                                       \
} while (0)

// ---------------- fused prep + W2-transpose kernel ----------------------------
#define P_W1   (2 * UU * VV / 4)
#define P_EMB  (VV * DD / 4)
#define P_WCAT (H6 * DD)
#define P_U    (2 * 4 * UU * 192)
#define P_TOT  (P_W1 + P_EMB + P_WCAT + P_U)
#define TR_BLK (VV / 32 * VV / 32)     // 62500
#define PREP_BLK ((P_TOT + 255) / 256)
#define PREPTR_GRID (TR_BLK + PREP_BLK)

__global__ void __launch_bounds__(256) prep_tr(
    const float* __restrict__ W2, __half* __restrict__ w2t,
    const float* __restrict__ W1, __half* __restrict__ w1h,
    const float* __restrict__ emb, __half* __restrict__ embh,
    const float* __restrict__ Wf_, const float* __restrict__ Wb_,
    const float* __restrict__ bfb, const float* __restrict__ bbb,
    __half* __restrict__ wcatt, float* __restrict__ bcat,
    const float* __restrict__ Uf, const float* __restrict__ Ub,
    float* __restrict__ uperm)
{
    __shared__ float t[32][33];
    int b = blockIdx.x;
    int tid = threadIdx.x;
    if (b < TR_BLK) {
        int bx = (b % (VV / 32)) * 32;
        int by = (b / (VV / 32)) * 32;
        int x = tid & 31, y0 = tid >> 5;
#pragma unroll
        for (int dy = 0; dy < 32; dy += 8)
            t[y0 + dy][x] = W2[(size_t)(by + y0 + dy) * VV + bx + x];
        __syncthreads();
#pragma unroll
        for (int dy = 0; dy < 32; dy += 8)
            w2t[(size_t)(bx + y0 + dy) * VV + by + x] = __float2half_rn(t[x][y0 + dy]);
        return;
    }
    int i = (b - TR_BLK) * 256 + tid;
    if (i < P_W1) {
        float4 v = ((const float4*)W1)[i];
        __half2 h0 = __floats2half2_rn(v.x, v.y);
        __half2 h1 = __floats2half2_rn(v.z, v.w);
        uint2 r;
        r.x = *reinterpret_cast<uint32_t*>(&h0);
        r.y = *reinterpret_cast<uint32_t*>(&h1);
        ((uint2*)w1h)[i] = r;
        return;
    }
    i -= P_W1;
    if (i < P_EMB) {
        float4 v = ((const float4*)emb)[i];
        __half2 h0 = __floats2half2_rn(v.x, v.y);
        __half2 h1 = __floats2half2_rn(v.z, v.w);
        uint2 r;
        r.x = *reinterpret_cast<uint32_t*>(&h0);
        r.y = *reinterpret_cast<uint32_t*>(&h1);
        ((uint2*)embh)[i] = r;
        return;
    }
    i -= P_EMB;
    if (i < P_WCAT) {
        int n = i / DD, k = i % DD;
        float v = (n < H3) ? Wf_[k * H3 + n] : Wb_[k * H3 + (n - H3)];
        wcatt[i] = __float2half_rn(v);
        if (i < H6)
            bcat[i] = (i < H3) ? bfb[i] : bbb[i - H3];
        return;
    }
    i -= P_WCAT;
    if (i < P_U) {
        int c = i % 192;
        int k = (i / 192) % UU;
        int r = (i / (192 * UU)) % 4;
        int dir = i / (192 * UU * 4);
        const float* Um = dir ? Ub : Uf;
        int col = (c < 64) ? (64 * r + c)
                : (c < 128) ? (UU + 64 * r + (c - 64))
                            : (2 * UU + 64 * r + (c - 128));
        uperm[i] = Um[k * H3 + col];
    }
}

// split-K reduce: wfth = fp16(sum of NSPLIT partials)
__global__ void wf_reduce(const float* __restrict__ partk, __half* __restrict__ wfth) {
    int i = blockIdx.x * 256 + threadIdx.x;
    const int n4 = VV * 2 * UU / 4;
    if (i >= n4) return;
    float4 s = ((const float4*)partk)[i];
#pragma unroll
    for (int z = 1; z < NSPLIT; z++) {
        float4 v = ((const float4*)(partk + (size_t)z * VV * 2 * UU))[i];
        s.x += v.x; s.y += v.y; s.z += v.z; s.w += v.w;
    }
    __half2 h0 = __floats2half2_rn(s.x, s.y);
    __half2 h1 = __floats2half2_rn(s.z, s.w);
    uint2 r;
    r.x = *reinterpret_cast<uint32_t*>(&h0);
    r.y = *reinterpret_cast<uint32_t*>(&h1);
    ((uint2*)wfth)[i] = r;
}

// ---------------- fp16 GEMM body (mma.sync m16n8k16, fp32 accum) --------------
#define HBM_ 128
#define HBN_ 256
#define HBK_ 32
#define HNST 4
#define HROWB 80
#define HASB (HBM_ * HROWB)
#define HBSB (HBN_ * HROWB)
#define HSTG (HASB + HBSB)
#define HGE_SMEM (HNST * HSTG)

__device__ __forceinline__ void gemm_body(
    const __half* __restrict__ A, int lda,
    const __half* __restrict__ Bt, int ldb,
    const float* __restrict__ bias, float* __restrict__ C,
    int M, int N, int K, int tile, unsigned char* sm)
{
    int ntiles = (N + HBN_ - 1) / HBN_;
    int mt = tile / ntiles, nt = tile % ntiles;
    int m0 = mt * HBM_, n0 = nt * HBN_;

    int tid = threadIdx.x;
    int lane = tid & 31;
    int wid = tid >> 5;
    int wm = wid >> 2;
    int wn = wid & 3;
    int g = lane >> 2;
    int t4 = lane & 3;

    uint32_t sbase = (uint32_t)__cvta_generic_to_shared(sm);

    float acc[4][8][4];
#pragma unroll
    for (int a = 0; a < 4; a++)
#pragma unroll
        for (int b = 0; b < 8; b++)
#pragma unroll
            for (int c = 0; c < 4; c++) acc[a][b][c] = 0.f;

    const int KT = K / HBK_;

    auto issue = [&](int kt, int slot) {
        int k0 = kt * HBK_;
        uint32_t ab = sbase + slot * HSTG;
        uint32_t bb = ab + HASB;
#pragma unroll
        for (int i = 0; i < 2; i++) {
            int ch = tid + i * 256;
            int r = ch >> 2, c16 = ch & 3;
            int ra = m0 + r; if (ra >= M) ra = M - 1;
            const __half* src = A + (size_t)ra * lda + k0 + c16 * 8;
            uint32_t dst = ab + (uint32_t)(r * HROWB + c16 * 16);
            asm volatile("cp.async.cg.shared.global [%0],[%1],16;\n" :: "r"(dst), "l"(src));
        }
#pragma unroll
        for (int i = 0; i < 4; i++) {
            int ch = tid + i * 256;
            int r = ch >> 2, c16 = ch & 3;
            int nb = n0 + r;
            int sz = (nb < N) ? 16 : 0;
            if (nb >= N) nb = N - 1;
            const __half* src = Bt + (size_t)nb * ldb + k0 + c16 * 8;
            uint32_t dst = bb + (uint32_t)(r * HROWB + c16 * 16);
            asm volatile("cp.async.cg.shared.global [%0],[%1],16,%2;\n" :: "r"(dst), "l"(src), "r"(sz));
        }
        asm volatile("cp.async.commit_group;\n");
    };

    auto docompute = [&](int slot) {
        const unsigned char* As = sm + slot * HSTG;
        const unsigned char* Bs = As + HASB;
#pragma unroll
        for (int kk = 0; kk < 2; kk++) {
            int kb = kk * 32 + t4 * 4;
            uint32_t af[4][4];
#pragma unroll
            for (int mi = 0; mi < 4; mi++) {
                int row = wm * 64 + mi * 16 + g;
                const unsigned char* p = As + row * HROWB + kb;
                af[mi][0] = *(const uint32_t*)(p);
                af[mi][1] = *(const uint32_t*)(p + 8 * HROWB);
                af[mi][2] = *(const uint32_t*)(p + 16);
                af[mi][3] = *(const uint32_t*)(p + 8 * HROWB + 16);
            }
            uint32_t bf[8][2];
#pragma unroll
            for (int ni = 0; ni < 8; ni++) {
                int nr = wn * 64 + ni * 8 + g;
                const unsigned char* p = Bs + nr * HROWB + kb;
                bf[ni][0] = *(const uint32_t*)(p);
                bf[ni][1] = *(const uint32_t*)(p + 16);
            }
#pragma unroll
            for (int mi = 0; mi < 4; mi++)
#pragma unroll
                for (int ni = 0; ni < 8; ni++) {
                    asm volatile(
                        "mma.sync.aligned.m16n8k16.row.col.f32.f16.f16.f32 "
                        "{%0,%1,%2,%3},{%4,%5,%6,%7},{%8,%9},{%0,%1,%2,%3};\n"
                        : "+f"(acc[mi][ni][0]), "+f"(acc[mi][ni][1]),
                          "+f"(acc[mi][ni][2]), "+f"(acc[mi][ni][3])
                        : "r"(af[mi][0]), "r"(af[mi][1]), "r"(af[mi][2]), "r"(af[mi][3]),
                          "r"(bf[ni][0]), "r"(bf[ni][1]));
                }
        }
    };

    issue(0, 0);
    if (KT > 1) issue(1, 1);
    if (KT > 2) issue(2, 2);

#pragma unroll 1
    for (int kt = 0; kt < KT; kt++) {
        if (kt + 1 < KT) {
            asm volatile("cp.async.wait_group %0;\n" :: "n"(HNST - 2));
        } else {
            asm volatile("cp.async.wait_group 0;\n");
        }
        __syncthreads();
        if (kt + HNST - 1 < KT)
            issue(kt + HNST - 1, (kt + HNST - 1) & (HNST - 1));
        docompute(kt & (HNST - 1));
    }

#pragma unroll
    for (int ni = 0; ni < 8; ni++) {
        int c = n0 + wn * 64 + ni * 8 + t4 * 2;
        if (c >= N) continue;
        float b0v = bias[c], b1v = bias[c + 1];
#pragma unroll
        for (int mi = 0; mi < 4; mi++) {
            int r = m0 + wm * 64 + mi * 16 + g;
            if (r >= M) continue;
            *reinterpret_cast<float2*>(&C[(size_t)r * N + c]) =
                make_float2(acc[mi][ni][0] + b0v, acc[mi][ni][1] + b1v);
            if (r + 8 < M)
                *reinterpret_cast<float2*>(&C[(size_t)(r + 8) * N + c]) =
                    make_float2(acc[mi][ni][2] + b0v, acc[mi][ni][3] + b1v);
        }
    }
}

// standalone GEMM (embW projection + final logits)
__global__ void __launch_bounds__(256) gemm_h0(
    const __half* __restrict__ A, int lda, const __half* __restrict__ Bt, int ldb,
    const float* __restrict__ bias, float* __restrict__ C,
    int M, int N, int K)
{
    extern __shared__ __align__(16) unsigned char sm[];
    gemm_body(A, lda, Bt, ldb, bias, C, M, N, K, blockIdx.x, sm);
}

// ---------------- megaW: WfT split-K GEMM + bias fuse (side stream) -----------
#define NWFT  (NSPLIT * 126)     // 630
#define NBIAS (VV / 8)           // 1000
#define MW_GRID (NWFT + NBIAS)

__global__ void __launch_bounds__(256) megaW(
    const __half* __restrict__ w2t, const __half* __restrict__ w1h,
    float* __restrict__ partk, const float* __restrict__ zb,
    const float* __restrict__ b1, const float* __restrict__ b2,
    float* __restrict__ bf)
{
    extern __shared__ __align__(16) unsigned char sm[];
    int b = blockIdx.x;
    if (b < NWFT) {
        int kz = b / 126, t = b % 126;
        gemm_body(w2t + (size_t)kz * KC, VV,
                  w1h + (size_t)kz * KC, VV,
                  zb, partk + (size_t)kz * VV * 2 * UU,
                  VV, 2 * UU, KC, t, sm);
    } else {
        int nb = b - NWFT;
        int n = nb * 8 + (threadIdx.x >> 5);
        int lane = threadIdx.x & 31;
        const __half2* row = (const __half2*)(w2t + (size_t)n * VV);
        const float2* b1p = (const float2*)b1;
        float acc = 0.f;
#pragma unroll 5
        for (int i = 0; i < VV / 64; i++) {
            int idx = i * 32 + lane;
            float2 f = __half22float2(row[idx]);
            float2 bb = b1p[idx];
            acc += bb.x * f.x + bb.y * f.y;
        }
#pragma unroll
        for (int off = 16; off > 0; off >>= 1)
            acc += __shfl_xor_sync(0xFFFFFFFF, acc, off);
        if (lane == 0) bf[n] = acc + b2[n];
    }
}

// ---------------- GRU: 384 threads, 8-way k-split, st.async sync (R13) --------
#define GRU_THREADS 384
#define GRU_SM_US   (UU * 192 * 4)              // 196608
#define GRU_SM_PART (16 * 192 * 4)              // 12288
#define GRU_SM_H    (2 * 2 * UU * 8)            // 8192
#define GRU_SMEM    (GRU_SM_US + GRU_SM_PART + GRU_SM_H + 16)
#define UREG 20

__global__ void __launch_bounds__(GRU_THREADS, 1) __cluster_dims__(4, 1, 1)
gru_scan(const float* __restrict__ embW, const float* __restrict__ uperm,
         const float* __restrict__ bf1, const float* __restrict__ bb1,
         const int* __restrict__ tokens, __half* __restrict__ hcat)
{
    extern __shared__ __align__(16) unsigned char smraw[];
    float* Us   = (float*)smraw;
    float* part = (float*)(smraw + GRU_SM_US);
    unsigned long long* hbuf =
        (unsigned long long*)(smraw + GRU_SM_US + GRU_SM_PART);
    uint32_t mb0 = (uint32_t)__cvta_generic_to_shared(smraw + GRU_SM_US + GRU_SM_PART + GRU_SM_H);

    int tid  = threadIdx.x;
    int cid  = blockIdx.x >> 2;
    int rank = blockIdx.x & 3;
    int bp   = cid & 15;
    int dir  = cid >> 4;
    int b0   = bp * 2;
    const float* bv = dir ? bb1 : bf1;

    {
        const float4* src = (const float4*)(uperm + (size_t)(dir * 4 + rank) * UU * 192);
        float4* dst = (float4*)Us;
        for (int i = tid; i < UU * 192 / 4; i += GRU_THREADS) dst[i] = src[i];
        for (int i = tid; i < 2 * 2 * UU; i += GRU_THREADS) hbuf[i] = 0ull;
    }
    if (tid == 0) { MBARRIER_INIT(mb0, 1); MBARRIER_INIT(mb0 + 8, 1); }
    __syncthreads();
    CLUSTER_ARRIVE();
    CLUSTER_WAIT();

    int kc = tid / 48;     // 0..7: k-range of 32
    int ct = tid % 48;     // 2 col-pairs (4 cols)
    int k0 = kc * 32;

    const ulonglong2* U2 = (const ulonglong2*)Us;
    ulonglong2 ur[UREG];
#pragma unroll
    for (int kk = 0; kk < UREG; kk++)
        ur[kk] = U2[(size_t)(k0 + kk) * 48 + ct];

    int jj = tid & 63;
    int ub = (tid >> 6) & 1;
    int j  = rank * 64 + jj;
    float bz = 0.f, br = 0.f, bh = 0.f;
    if (tid < 128) { bz = bv[j]; br = bv[UU + j]; bh = bv[2 * UU + j]; }

    uint32_t hl = (uint32_t)__cvta_generic_to_shared(hbuf);
    uint32_t hpeer[4], mpeer[4];
#pragma unroll
    for (int r = 0; r < 4; r++) {
        hpeer[r] = mapa_u32(hl, r);
        mpeer[r] = mapa_u32(mb0, r);
    }

    int ph0 = 0, ph1 = 0;

    for (int i = 0; i < SS; i++) {
        int p = i & 1;
        if (tid == 0 && i < SS - 1)
            MBARRIER_EXPECT_TX(mb0 + (p ^ 1) * 8, 4096);

        float pz = 0.f, pr = 0.f, phx = 0.f; int tk = 1;
        size_t rb = 0;
        if (tid < 128) {
            int s = dir ? (SS - 1 - i) : i;
            rb = (size_t)(b0 + ub) * SS + s;
            tk = tokens[rb];
            const float* xr = embW + (size_t)tk * H6 + dir * H3;
            pz = xr[j]; pr = xr[UU + j]; phx = xr[2 * UU + j];
        }

        if (i > 0) {
            if (p == 0) { MBARRIER_WAIT_PARITY(mb0,     ph0); ph0 ^= 1; }
            else        { MBARRIER_WAIT_PARITY(mb0 + 8, ph1); ph1 ^= 1; }
        }

        {
            unsigned long long a00 = 0, a01 = 0, a10 = 0, a11 = 0;
            const ulonglong2* h0 = (const ulonglong2*)(hbuf + (p * 2 + 0) * UU) + kc * 16;
            const ulonglong2* h1 = (const ulonglong2*)(hbuf + (p * 2 + 1) * UU) + kc * 16;
#pragma unroll
            for (int kk = 0; kk < UREG / 2; kk++) {
                ulonglong2 uA = ur[2 * kk];
                ulonglong2 uB = ur[2 * kk + 1];
                ulonglong2 hA = h0[kk];
                ulonglong2 hB = h1[kk];
                FMA2(a00, uA.x, hA.x); FMA2(a01, uA.y, hA.x);
                FMA2(a10, uA.x, hB.x); FMA2(a11, uA.y, hB.x);
                FMA2(a00, uB.x, hA.y); FMA2(a01, uB.y, hA.y);
                FMA2(a10, uB.x, hB.y); FMA2(a11, uB.y, hB.y);
            }
            const ulonglong2* up = U2 + (size_t)(k0 + UREG) * 48 + ct;
#pragma unroll
            for (int kk = UREG / 2; kk < 16; kk++) {
                ulonglong2 uA = up[0];
                ulonglong2 uB = up[48];
                up += 96;
                ulonglong2 hA = h0[kk];
                ulonglong2 hB = h1[kk];
                FMA2(a00, uA.x, hA.x); FMA2(a01, uA.y, hA.x);
                FMA2(a10, uA.x, hB.x); FMA2(a11, uA.y, hB.x);
                FMA2(a00, uB.x, hA.y); FMA2(a01, uB.y, hA.y);
                FMA2(a10, uB.x, hB.y); FMA2(a11, uB.y, hB.y);
            }
            float2 p00 = unpack2(a00), p01 = unpack2(a01);
            float2 p10 = unpack2(a10), p11 = unpack2(a11);
            ((float4*)(part + (kc * 2 + 0) * 192))[ct] = make_float4(p00.x, p00.y, p01.x, p01.y);
            ((float4*)(part + (kc * 2 + 1) * 192))[ct] = make_float4(p10.x, p10.y, p11.x, p11.y);
        }
        __syncthreads();

        if (tid < 128) {
            float iz = 0.f, ir = 0.f, ih = 0.f;
#pragma unroll
            for (int q = 0; q < 8; q++) {
                const float* pr_ = part + (2 * q + ub) * 192;
                iz += pr_[jj];
                ir += pr_[64 + jj];
                ih += pr_[128 + jj];
            }

            float hold = ((const float*)&hbuf[(p * 2 + ub) * UU + j])[0];
            float z = 1.f / (1.f + __expf(-(pz + iz + bz)));
            float g = 1.f / (1.f + __expf(-(pr + ir + br)));
            float c = tanhf(phx + g * (ih + bh));
            float hn = z * hold + (1.f - z) * c;
            if (tk == 0) hn = hold;

            if (i < SS - 1) {
                unsigned long long hd = pack2(hn, hn);
                uint32_t off = (uint32_t)(((p ^ 1) * 2 + ub) * UU + j) * 8u;
                uint32_t mboff = (uint32_t)((p ^ 1) * 8);
#pragma unroll
                for (int r = 0; r < 4; r++)
                    ST_ASYNC_U64(hpeer[r] + off, hd, mpeer[r] + mboff);
            }
            hcat[rb * (2 * UU) + dir * UU + j] = __float2half_rn(hn);
        }
    }
    CLUSTER_ARRIVE();
    CLUSTER_WAIT();
}

// ---------------- host launcher ----------------------------------------------
extern "C" void kernel_launch(void* const* d_in, const int* in_sizes, int n_in,
                              void* d_out, int out_size)
{
    const int*   tokens = (const int*)d_in[0];
    const float* emb    = (const float*)d_in[1];
    const float* W_f    = (const float*)d_in[2];
    const float* U_f    = (const float*)d_in[3];
    const float* b_f    = (const float*)d_in[4];
    const float* W_b    = (const float*)d_in[5];
    const float* U_b    = (const float*)d_in[6];
    const float* b_b    = (const float*)d_in[7];
    const float* W1     = (const float*)d_in[8];
    const float* b1     = (const float*)d_in[9];
    const float* W2     = (const float*)d_in[10];
    const float* b2     = (const float*)d_in[11];
    float* out = (float*)d_out;

    __half *w1h, *w2t, *embh, *wcatt, *hcat, *wfth;
    float *bcat, *embw, *bfv, *uperm, *partk, *zb;
    cudaGetSymbolAddress((void**)&w1h,   g_w1h);
    cudaGetSymbolAddress((void**)&w2t,   g_w2t);
    cudaGetSymbolAddress((void**)&embh,  g_embh);
    cudaGetSymbolAddress((void**)&wcatt, g_wcatt);
    cudaGetSymbolAddress((void**)&bcat,  g_bcat);
    cudaGetSymbolAddress((void**)&embw,  g_embw);
    cudaGetSymbolAddress((void**)&hcat,  g_hcat);
    cudaGetSymbolAddress((void**)&wfth,  g_wfth);
    cudaGetSymbolAddress((void**)&bfv,   g_bf);
    cudaGetSymbolAddress((void**)&uperm, g_uperm);
    cudaGetSymbolAddress((void**)&partk, g_partk);
    cudaGetSymbolAddress((void**)&zb,    g_zb);

    cudaFuncSetAttribute(megaW,   cudaFuncAttributeMaxDynamicSharedMemorySize, HGE_SMEM);
    cudaFuncSetAttribute(gemm_h0, cudaFuncAttributeMaxDynamicSharedMemorySize, HGE_SMEM);
    cudaFuncSetAttribute(gru_scan, cudaFuncAttributeMaxDynamicSharedMemorySize, GRU_SMEM);

    // 1) fused prep: W2 transpose (fp16) + fp16 conversions + concat + U permute
    prep_tr<<<PREPTR_GRID, 256>>>(W2, w2t, W1, w1h, emb, embh,
                                  W_f, W_b, b_f, b_b, wcatt, bcat,
                                  U_f, U_b, uperm);
    cudaEventRecord(g_si.ev1, 0);

    // 2a) main stream: embW GEMM -> GRU scan (launched first: scheduler hint)
    {
        int mtiles = (VV + HBM_ - 1) / HBM_;     // 63
        int ntiles = H6 / HBN_;                  // 6
        gemm_h0<<<mtiles * ntiles, 256, HGE_SMEM>>>(embh, DD, wcatt, DD,
                                                    bcat, embw, VV, H6, DD);
    }
    gru_scan<<<128, GRU_THREADS, GRU_SMEM>>>(embw, uperm, b_f + H3, b_b + H3,
                                             tokens, hcat);

    // 2b) side stream (overlaps GRU): WfT split-K GEMM + bias fuse + reduce
    cudaStreamWaitEvent(g_si.s1, g_si.ev1, 0);
    megaW<<<MW_GRID, 256, HGE_SMEM, g_si.s1>>>(w2t, w1h, partk, zb, b1, b2, bfv);
    wf_reduce<<<(VV * 2 * UU / 4 + 255) / 256, 256, 0, g_si.s1>>>(partk, wfth);
    cudaEventRecord(g_si.ev2, g_si.s1);

    // 3) join: logits = hcat @ Wf + bf -> output
    cudaStreamWaitEvent(0, g_si.ev2, 0);
    {
        int mtiles = MR / HBM_;                  // 64
        int ntiles = (VV + HBN_ - 1) / HBN_;     // 32
        gemm_h0<<<mtiles * ntiles, 256, HGE_SMEM>>>(hcat, 2 * UU, wfth, 2 * UU,
                                                    bfv, out, MR, VV, 2 * UU);
    }
}